// round 6
// baseline (speedup 1.0000x reference)
#include <cuda_runtime.h>
#include <cuda_bf16.h>
#include <cstdint>

#define B_ 4
#define N_ 4096
#define C_ 256
#define M_ (B_ * N_)

#define ROWB 144      // bytes per SMEM row (64 bf16 = 128B + 16B pad)

// SMEM layout (dynamic) for k_gemm:
#define SM_AHI 0
#define SM_ALO 18432
#define SM_B0  36864            // buffer 0: hi at +0, lo at +36864
#define BUFSZ  73728
#define SM_TOTAL (36864 + 2 * BUFSZ)   // 184320

#define GRID_GEMM 128

// ---------------- device scratch ----------------
__device__ float g_Wpart[4][C_ * C_];      // per-kslab partials of Wv@Wo
__device__ __nv_bfloat16 g_Bhi[C_ * C_];   // W^T hi, [n][k]
__device__ __nv_bfloat16 g_Blo[C_ * C_];   // W^T lo, [n][k]
__device__ float g_sum[B_ * C_];
__device__ float g_sumsq[B_ * C_];
__device__ unsigned g_bar;                 // grid barrier counter (zeroed by k_split)

__device__ __forceinline__ uint32_t smem_u32(const void* p) {
    uint32_t a;
    asm("{ .reg .u64 t; cvta.to.shared.u64 t, %1; cvt.u32.u64 %0, t; }" : "=r"(a) : "l"(p));
    return a;
}
__device__ __forceinline__ void cp16(uint32_t dst, const void* src) {
    asm volatile("cp.async.cg.shared.global [%0], [%1], 16;" :: "r"(dst), "l"(src));
}
__device__ __forceinline__ void cp_commit() {
    asm volatile("cp.async.commit_group;" ::: "memory");
}
template <int N> __device__ __forceinline__ void cp_wait() {
    asm volatile("cp.async.wait_group %0;" :: "n"(N) : "memory");
}
__device__ __forceinline__ void ldmx4(uint32_t* r, uint32_t addr) {
    asm volatile("ldmatrix.sync.aligned.m8n8.x4.shared.b16 {%0,%1,%2,%3}, [%4];"
                 : "=r"(r[0]), "=r"(r[1]), "=r"(r[2]), "=r"(r[3]) : "r"(addr));
}
__device__ __forceinline__ void ldmx2(uint32_t* r, uint32_t addr) {
    asm volatile("ldmatrix.sync.aligned.m8n8.x2.shared.b16 {%0,%1}, [%2];"
                 : "=r"(r[0]), "=r"(r[1]) : "r"(addr));
}
__device__ __forceinline__ void mma16816(float* c, const uint32_t* a, const uint32_t* b) {
    asm volatile(
        "mma.sync.aligned.m16n8k16.row.col.f32.bf16.bf16.f32 "
        "{%0,%1,%2,%3}, {%4,%5,%6,%7}, {%8,%9}, {%0,%1,%2,%3};"
        : "+f"(c[0]), "+f"(c[1]), "+f"(c[2]), "+f"(c[3])
        : "r"(a[0]), "r"(a[1]), "r"(a[2]), "r"(a[3]), "r"(b[0]), "r"(b[1]));
}

// ---------------------------------------------------------------------------
// K1: partial W = Wv@Wo over a 64-wide k-slab. grid (32 rowgroups, 4 kslabs).
// ---------------------------------------------------------------------------
__global__ __launch_bounds__(256) void k_prepmm(const float* __restrict__ Wv,
                                                const float* __restrict__ Wo) {
    __shared__ float s_wv[8][64];
    int t = threadIdx.x;
    int i0 = blockIdx.x * 8;
    int k0 = blockIdx.y * 64;

    #pragma unroll
    for (int e = t; e < 512; e += 256)
        s_wv[e >> 6][e & 63] = Wv[(i0 + (e >> 6)) * C_ + k0 + (e & 63)];
    __syncthreads();

    float acc[8] = {};
    #pragma unroll 16
    for (int kk = 0; kk < 64; kk++) {
        float wo = Wo[(k0 + kk) * C_ + t];
        #pragma unroll
        for (int r = 0; r < 8; r++) acc[r] += s_wv[r][kk] * wo;
    }
    float* dst = &g_Wpart[blockIdx.y][i0 * C_ + t];
    #pragma unroll
    for (int r = 0; r < 8; r++) dst[r * C_] = acc[r];
}

// ---------------------------------------------------------------------------
// K2: sum partials, emit transposed bf16 hi/lo; zero stats + barrier.
// (Per-channel bias cancels exactly through the N-axis LayerNorm -> dropped.)
// ---------------------------------------------------------------------------
__global__ __launch_bounds__(256) void k_split() {
    int base = blockIdx.x * 1024 + threadIdx.x * 4;
    #pragma unroll
    for (int u = 0; u < 4; u++) {
        int idx = base + u;
        float w = g_Wpart[0][idx] + g_Wpart[1][idx] + g_Wpart[2][idx] + g_Wpart[3][idx];
        int i = idx >> 8;       // k index
        int j = idx & 255;      // n index
        __nv_bfloat16 h = __float2bfloat16(w);
        g_Bhi[j * C_ + i] = h;
        g_Blo[j * C_ + i] = __float2bfloat16(w - __bfloat162float(h));
    }
    if (blockIdx.x < 2) {
        int i = blockIdx.x * 1024 + threadIdx.x * 4;
        if (i < B_ * C_) {
            *(float4*)&g_sum[i] = make_float4(0.f, 0.f, 0.f, 0.f);
            *(float4*)&g_sumsq[i] = make_float4(0.f, 0.f, 0.f, 0.f);
        }
    }
    if (blockIdx.x == 0 && threadIdx.x == 0) g_bar = 0u;
}

// ---------------------------------------------------------------------------
// K3: y = X @ W (split-bf16 HMMA) fully fused:
//     stats atomics -> single-wave grid barrier -> LN+relu+residual from regs.
// ---------------------------------------------------------------------------
__global__ __launch_bounds__(256, 1) void k_gemm(const float* __restrict__ X,
                                                 const float* __restrict__ ls,
                                                 const float* __restrict__ lb,
                                                 float* __restrict__ out) {
    extern __shared__ char smem[];
    uint32_t sb = smem_u32(smem);
    int t = threadIdx.x, wid = t >> 5, lane = t & 31;
    int warpM = wid >> 2, warpN = wid & 3;
    int m0 = blockIdx.x * 128;
    int q = t & 3, rr = t >> 2;          // loader coords

    float acc[4][8][4];
    #pragma unroll
    for (int i = 0; i < 4; i++)
        #pragma unroll
        for (int j = 0; j < 8; j++)
            #pragma unroll
            for (int r = 0; r < 4; r++) acc[i][j][r] = 0.f;

    uint32_t aBase = sb + SM_AHI +
        (warpM * 64 + ((lane >> 3) & 1) * 8 + (lane & 7)) * ROWB + (lane >> 4) * 16;

    auto issueB = [&](int c, int buf) {
        uint32_t bhi = sb + SM_B0 + buf * BUFSZ;
        uint32_t blo = bhi + 36864;
        const char* shi = (const char*)g_Bhi + c * 128 + q * 32;
        const char* slo = (const char*)g_Blo + c * 128 + q * 32;
        #pragma unroll
        for (int it = 0; it < 4; it++) {
            int row = it * 64 + rr;
            uint32_t d = row * ROWB + q * 32;
            const char* sh = shi + (size_t)row * 512;
            const char* sl = slo + (size_t)row * 512;
            cp16(bhi + d, sh);       cp16(bhi + d + 16, sh + 16);
            cp16(blo + d, sl);       cp16(blo + d + 16, sl + 16);
        }
        cp_commit();
    };
    float areg[32];
    auto loadA = [&](int c) {
        #pragma unroll
        for (int p = 0; p < 2; p++) {
            const float* src = X + (size_t)(m0 + p * 64 + rr) * C_ + c * 64 + q * 16;
            #pragma unroll
            for (int i = 0; i < 4; i++)
                *(float4*)&areg[p * 16 + i * 4] = *(const float4*)(src + i * 4);
        }
    };
    auto storeA = [&]() {
        #pragma unroll
        for (int p = 0; p < 2; p++) {
            int row = p * 64 + rr;
            __nv_bfloat16 h[16], l[16];
            #pragma unroll
            for (int i = 0; i < 16; i++) {
                float v = areg[p * 16 + i];
                h[i] = __float2bfloat16(v);
                l[i] = __float2bfloat16(v - __bfloat162float(h[i]));
            }
            char* dh = smem + SM_AHI + row * ROWB + q * 32;
            char* dl = smem + SM_ALO + row * ROWB + q * 32;
            *(uint4*)dh = *(uint4*)&h[0]; *(uint4*)(dh + 16) = *(uint4*)&h[8];
            *(uint4*)dl = *(uint4*)&l[0]; *(uint4*)(dl + 16) = *(uint4*)&l[8];
        }
    };

    issueB(0, 0);
    loadA(0);

    for (int c = 0; c < 4; c++) {
        if (c < 3) issueB(c + 1, (c + 1) & 1);
        storeA();
        if (c < 3) cp_wait<1>(); else cp_wait<0>();
        __syncthreads();
        if (c < 3) loadA(c + 1);           // DRAM latency hides under MMAs

        uint32_t bBase = sb + SM_B0 + (c & 1) * BUFSZ +
            (warpN * 64 + (lane & 7)) * ROWB + ((lane >> 3) & 1) * 16;
        #pragma unroll
        for (int ks = 0; ks < 4; ks++) {
            uint32_t ah[4][4], al[4][4];
            #pragma unroll
            for (int ms = 0; ms < 4; ms++) {
                uint32_t addr = aBase + ms * (16 * ROWB) + ks * 32;
                ldmx4(ah[ms], addr);
                ldmx4(al[ms], addr + (SM_ALO - SM_AHI));
            }
            #pragma unroll
            for (int ns = 0; ns < 8; ns++) {
                uint32_t bh[2], bl[2];
                uint32_t addr = bBase + ns * (8 * ROWB) + ks * 32;
                ldmx2(bh, addr);
                ldmx2(bl, addr + 36864);
                #pragma unroll
                for (int ms = 0; ms < 4; ms++) {
                    mma16816(acc[ms][ns], ah[ms], bh);
                    mma16816(acc[ms][ns], ah[ms], bl);
                    mma16816(acc[ms][ns], al[ms], bh);
                }
            }
        }
        __syncthreads();
    }

    // ---- column stats from registers, atomics into g_sum/g_sumsq ----
    int b = m0 >> 12;
    int gid = lane >> 2, tig = lane & 3;
    #pragma unroll
    for (int ns = 0; ns < 8; ns++) {
        float s0 = 0.f, s1 = 0.f, q0 = 0.f, q1 = 0.f;
        #pragma unroll
        for (int ms = 0; ms < 4; ms++)
            #pragma unroll
            for (int half = 0; half < 2; half++) {
                float v0 = acc[ms][ns][half * 2 + 0];
                float v1 = acc[ms][ns][half * 2 + 1];
                s0 += v0; q0 += v0 * v0;
                s1 += v1; q1 += v1 * v1;
            }
        #pragma unroll
        for (int off = 4; off < 32; off <<= 1) {
            s0 += __shfl_xor_sync(0xFFFFFFFFu, s0, off);
            s1 += __shfl_xor_sync(0xFFFFFFFFu, s1, off);
            q0 += __shfl_xor_sync(0xFFFFFFFFu, q0, off);
            q1 += __shfl_xor_sync(0xFFFFFFFFu, q1, off);
        }
        if (gid == 0) {
            int col = warpN * 64 + ns * 8 + tig * 2;
            atomicAdd(&g_sum[b * C_ + col],     s0);
            atomicAdd(&g_sum[b * C_ + col + 1], s1);
            atomicAdd(&g_sumsq[b * C_ + col],     q0);
            atomicAdd(&g_sumsq[b * C_ + col + 1], q1);
        }
    }

    // ---- single-wave grid barrier (128 CTAs, 1/SM, guaranteed resident) ----
    __threadfence();
    __syncthreads();
    if (t == 0) {
        atomicAdd(&g_bar, 1u);
        while (*(volatile unsigned*)&g_bar < GRID_GEMM) { }
    }
    __syncthreads();
    __threadfence();

    // ---- fused apply: out = relu((y - mean)*rstd*ls + lb) + X ----
    #pragma unroll
    for (int ns = 0; ns < 8; ns++) {
        int col = warpN * 64 + ns * 8 + tig * 2;
        float sm0 = g_sum[b * C_ + col],   sm1 = g_sum[b * C_ + col + 1];
        float sq0 = g_sumsq[b * C_ + col], sq1 = g_sumsq[b * C_ + col + 1];
        const float inv = 1.f / N_;
        float mu0 = sm0 * inv, mu1 = sm1 * inv;
        float rs0 = rsqrtf(sq0 * inv - mu0 * mu0 + 1e-6f);
        float rs1 = rsqrtf(sq1 * inv - mu1 * mu1 + 1e-6f);
        float sc0 = ls[col] * rs0, sc1 = ls[col + 1] * rs1;
        float bb0 = lb[col], bb1 = lb[col + 1];

        #pragma unroll
        for (int ms = 0; ms < 4; ms++) {
            #pragma unroll
            for (int half = 0; half < 2; half++) {
                int row = m0 + warpM * 64 + ms * 16 + half * 8 + gid;
                const float2 xv = *(const float2*)(X + (size_t)row * C_ + col);
                float2 o;
                o.x = fmaxf((acc[ms][ns][half * 2 + 0] - mu0) * sc0 + bb0, 0.f) + xv.x;
                o.y = fmaxf((acc[ms][ns][half * 2 + 1] - mu1) * sc1 + bb1, 0.f) + xv.y;
                *(float2*)(out + (size_t)row * C_ + col) = o;
            }
        }
    }
}

// ---------------------------------------------------------------------------
extern "C" void kernel_launch(void* const* d_in, const int* in_sizes, int n_in,
                              void* d_out, int out_size) {
    // order: inputs, mask, Wq, bq, Wk, bk, Wv, bv, Wo, bo, ln_scale, ln_bias
    const float* X  = (const float*)d_in[0];
    const float* Wv = (const float*)d_in[6];
    const float* Wo = (const float*)d_in[8];
    const float* ls = (const float*)d_in[10];
    const float* lb = (const float*)d_in[11];
    float* out = (float*)d_out;

    cudaFuncSetAttribute(k_gemm, cudaFuncAttributeMaxDynamicSharedMemorySize,
                         SM_TOTAL);

    k_prepmm<<<dim3(32, 4), 256>>>(Wv, Wo);
    k_split<<<64, 256>>>();
    k_gemm<<<GRID_GEMM, 256, SM_TOTAL>>>(X, ls, lb, out);
}

// round 7
// speedup vs baseline: 1.1096x; 1.1096x over previous
#include <cuda_runtime.h>
#include <cuda_bf16.h>
#include <cstdint>

#define B_ 4
#define N_ 4096
#define C_ 256
#define M_ (B_ * N_)

#define ROWB 144      // bytes per SMEM row (64 bf16 = 128B + 16B pad)

// SMEM layout (dynamic) for k_gemm:
#define SM_AHI 0
#define SM_ALO 18432
#define SM_B0  36864            // buffer 0: hi at +0, lo at +36864
#define BUFSZ  73728
#define SM_TOTAL (36864 + 2 * BUFSZ)   // 184320

#define GRID_GEMM 128
#define YSTRIDE 260             // fp32 words per staged y row (padded)

// ---------------- device scratch ----------------
__device__ float g_Wpart[8][C_ * C_];      // per-kslab partials of Wv@Wo
__device__ __nv_bfloat16 g_Bhi[C_ * C_];   // W^T hi, [n][k]
__device__ __nv_bfloat16 g_Blo[C_ * C_];   // W^T lo, [n][k]
__device__ float g_sum[B_ * C_];
__device__ float g_sumsq[B_ * C_];
__device__ unsigned g_bar;                 // grid barrier (zeroed by k_split)

__device__ __forceinline__ uint32_t smem_u32(const void* p) {
    uint32_t a;
    asm("{ .reg .u64 t; cvta.to.shared.u64 t, %1; cvt.u32.u64 %0, t; }" : "=r"(a) : "l"(p));
    return a;
}
__device__ __forceinline__ void cp16(uint32_t dst, const void* src) {
    asm volatile("cp.async.cg.shared.global [%0], [%1], 16;" :: "r"(dst), "l"(src));
}
__device__ __forceinline__ void cp_commit() {
    asm volatile("cp.async.commit_group;" ::: "memory");
}
template <int N> __device__ __forceinline__ void cp_wait() {
    asm volatile("cp.async.wait_group %0;" :: "n"(N) : "memory");
}
__device__ __forceinline__ void ldmx4(uint32_t* r, uint32_t addr) {
    asm volatile("ldmatrix.sync.aligned.m8n8.x4.shared.b16 {%0,%1,%2,%3}, [%4];"
                 : "=r"(r[0]), "=r"(r[1]), "=r"(r[2]), "=r"(r[3]) : "r"(addr));
}
__device__ __forceinline__ void ldmx2(uint32_t* r, uint32_t addr) {
    asm volatile("ldmatrix.sync.aligned.m8n8.x2.shared.b16 {%0,%1}, [%2];"
                 : "=r"(r[0]), "=r"(r[1]) : "r"(addr));
}
__device__ __forceinline__ void mma16816(float* c, const uint32_t* a, const uint32_t* b) {
    asm volatile(
        "mma.sync.aligned.m16n8k16.row.col.f32.bf16.bf16.f32 "
        "{%0,%1,%2,%3}, {%4,%5,%6,%7}, {%8,%9}, {%0,%1,%2,%3};"
        : "+f"(c[0]), "+f"(c[1]), "+f"(c[2]), "+f"(c[3])
        : "r"(a[0]), "r"(a[1]), "r"(a[2]), "r"(a[3]), "r"(b[0]), "r"(b[1]));
}

// ---------------------------------------------------------------------------
// K1: partial W = Wv@Wo over a 32-wide k-slab. grid (32 rowgroups, 8 kslabs)
// = 256 CTAs -> 2 CTAs/SM for latency hiding.
// ---------------------------------------------------------------------------
__global__ __launch_bounds__(256) void k_prepmm(const float* __restrict__ Wv,
                                                const float* __restrict__ Wo) {
    __shared__ float s_wv[8][32];
    int t = threadIdx.x;
    int i0 = blockIdx.x * 8;
    int k0 = blockIdx.y * 32;

    if (t < 256) {
        // 8 rows x 32 k of Wv
        s_wv[t >> 5][t & 31] = Wv[(i0 + (t >> 5)) * C_ + k0 + (t & 31)];
    }
    __syncthreads();

    float acc[8] = {};
    #pragma unroll
    for (int kk = 0; kk < 32; kk++) {
        float wo = Wo[(k0 + kk) * C_ + t];
        #pragma unroll
        for (int r = 0; r < 8; r++) acc[r] += s_wv[r][kk] * wo;
    }
    float* dst = &g_Wpart[blockIdx.y][i0 * C_ + t];
    #pragma unroll
    for (int r = 0; r < 8; r++) dst[r * C_] = acc[r];
}

// ---------------------------------------------------------------------------
// K2: sum 8 partials, emit transposed bf16 hi/lo; zero stats + barrier.
// (Per-channel bias cancels exactly through the N-axis LayerNorm -> dropped.)
// ---------------------------------------------------------------------------
__global__ __launch_bounds__(256) void k_split() {
    int base = blockIdx.x * 1024 + threadIdx.x * 4;
    #pragma unroll
    for (int u = 0; u < 4; u++) {
        int idx = base + u;
        float w = 0.f;
        #pragma unroll
        for (int s = 0; s < 8; s++) w += g_Wpart[s][idx];
        int i = idx >> 8;       // k index
        int j = idx & 255;      // n index
        __nv_bfloat16 h = __float2bfloat16(w);
        g_Bhi[j * C_ + i] = h;
        g_Blo[j * C_ + i] = __float2bfloat16(w - __bfloat162float(h));
    }
    if (blockIdx.x < 2) {
        int i = blockIdx.x * 1024 + threadIdx.x * 4;
        if (i < B_ * C_) {
            *(float4*)&g_sum[i] = make_float4(0.f, 0.f, 0.f, 0.f);
            *(float4*)&g_sumsq[i] = make_float4(0.f, 0.f, 0.f, 0.f);
        }
    }
    if (blockIdx.x == 0 && threadIdx.x == 0) g_bar = 0u;
}

// ---------------------------------------------------------------------------
// K3: y = X @ W (split-bf16 HMMA) fully fused:
//     stats atomics -> grid barrier (overlapped with smem y staging)
//     -> coalesced LN+relu+residual apply from smem.
// ---------------------------------------------------------------------------
__global__ __launch_bounds__(256, 1) void k_gemm(const float* __restrict__ X,
                                                 const float* __restrict__ ls,
                                                 const float* __restrict__ lb,
                                                 float* __restrict__ out) {
    extern __shared__ char smem[];
    uint32_t sb = smem_u32(smem);
    int t = threadIdx.x, wid = t >> 5, lane = t & 31;
    int warpM = wid >> 2, warpN = wid & 3;
    int m0 = blockIdx.x * 128;
    int q = t & 3, rr = t >> 2;          // loader coords

    float acc[4][8][4];
    #pragma unroll
    for (int i = 0; i < 4; i++)
        #pragma unroll
        for (int j = 0; j < 8; j++)
            #pragma unroll
            for (int r = 0; r < 4; r++) acc[i][j][r] = 0.f;

    uint32_t aBase = sb + SM_AHI +
        (warpM * 64 + ((lane >> 3) & 1) * 8 + (lane & 7)) * ROWB + (lane >> 4) * 16;

    auto issueB = [&](int c, int buf) {
        uint32_t bhi = sb + SM_B0 + buf * BUFSZ;
        uint32_t blo = bhi + 36864;
        const char* shi = (const char*)g_Bhi + c * 128 + q * 32;
        const char* slo = (const char*)g_Blo + c * 128 + q * 32;
        #pragma unroll
        for (int it = 0; it < 4; it++) {
            int row = it * 64 + rr;
            uint32_t d = row * ROWB + q * 32;
            const char* sh = shi + (size_t)row * 512;
            const char* sl = slo + (size_t)row * 512;
            cp16(bhi + d, sh);       cp16(bhi + d + 16, sh + 16);
            cp16(blo + d, sl);       cp16(blo + d + 16, sl + 16);
        }
        cp_commit();
    };
    float areg[32];
    auto loadA = [&](int c) {
        #pragma unroll
        for (int p = 0; p < 2; p++) {
            const float* src = X + (size_t)(m0 + p * 64 + rr) * C_ + c * 64 + q * 16;
            #pragma unroll
            for (int i = 0; i < 4; i++)
                *(float4*)&areg[p * 16 + i * 4] = *(const float4*)(src + i * 4);
        }
    };
    auto storeA = [&]() {
        #pragma unroll
        for (int p = 0; p < 2; p++) {
            int row = p * 64 + rr;
            __nv_bfloat16 h[16], l[16];
            #pragma unroll
            for (int i = 0; i < 16; i++) {
                float v = areg[p * 16 + i];
                h[i] = __float2bfloat16(v);
                l[i] = __float2bfloat16(v - __bfloat162float(h[i]));
            }
            char* dh = smem + SM_AHI + row * ROWB + q * 32;
            char* dl = smem + SM_ALO + row * ROWB + q * 32;
            *(uint4*)dh = *(uint4*)&h[0]; *(uint4*)(dh + 16) = *(uint4*)&h[8];
            *(uint4*)dl = *(uint4*)&l[0]; *(uint4*)(dl + 16) = *(uint4*)&l[8];
        }
    };

    issueB(0, 0);
    loadA(0);

    for (int c = 0; c < 4; c++) {
        if (c < 3) issueB(c + 1, (c + 1) & 1);
        storeA();
        if (c < 3) cp_wait<1>(); else cp_wait<0>();
        __syncthreads();
        if (c < 3) loadA(c + 1);           // DRAM latency hides under MMAs

        uint32_t bBase = sb + SM_B0 + (c & 1) * BUFSZ +
            (warpN * 64 + (lane & 7)) * ROWB + ((lane >> 3) & 1) * 16;
        #pragma unroll
        for (int ks = 0; ks < 4; ks++) {
            uint32_t ah[4][4], al[4][4];
            #pragma unroll
            for (int ms = 0; ms < 4; ms++) {
                uint32_t addr = aBase + ms * (16 * ROWB) + ks * 32;
                ldmx4(ah[ms], addr);
                ldmx4(al[ms], addr + (SM_ALO - SM_AHI));
            }
            #pragma unroll
            for (int ns = 0; ns < 8; ns++) {
                uint32_t bh[2], bl[2];
                uint32_t addr = bBase + ns * (8 * ROWB) + ks * 32;
                ldmx2(bh, addr);
                ldmx2(bl, addr + 36864);
                #pragma unroll
                for (int ms = 0; ms < 4; ms++) {
                    mma16816(acc[ms][ns], ah[ms], bh);
                    mma16816(acc[ms][ns], ah[ms], bl);
                    mma16816(acc[ms][ns], al[ms], bh);
                }
            }
        }
        __syncthreads();
    }

    // ---- column stats from registers, atomics into g_sum/g_sumsq ----
    int b = m0 >> 12;
    int gid = lane >> 2, tig = lane & 3;
    #pragma unroll
    for (int ns = 0; ns < 8; ns++) {
        float s0 = 0.f, s1 = 0.f, q0 = 0.f, q1 = 0.f;
        #pragma unroll
        for (int ms = 0; ms < 4; ms++)
            #pragma unroll
            for (int half = 0; half < 2; half++) {
                float v0 = acc[ms][ns][half * 2 + 0];
                float v1 = acc[ms][ns][half * 2 + 1];
                s0 += v0; q0 += v0 * v0;
                s1 += v1; q1 += v1 * v1;
            }
        #pragma unroll
        for (int off = 4; off < 32; off <<= 1) {
            s0 += __shfl_xor_sync(0xFFFFFFFFu, s0, off);
            s1 += __shfl_xor_sync(0xFFFFFFFFu, s1, off);
            q0 += __shfl_xor_sync(0xFFFFFFFFu, q0, off);
            q1 += __shfl_xor_sync(0xFFFFFFFFu, q1, off);
        }
        if (gid == 0) {
            int col = warpN * 64 + ns * 8 + tig * 2;
            atomicAdd(&g_sum[b * C_ + col],     s0);
            atomicAdd(&g_sum[b * C_ + col + 1], s1);
            atomicAdd(&g_sumsq[b * C_ + col],     q0);
            atomicAdd(&g_sumsq[b * C_ + col + 1], q1);
        }
    }

    // ---- arrive, then stage y into smem while other CTAs drain ----
    __threadfence();
    __syncthreads();
    if (t == 0) atomicAdd(&g_bar, 1u);

    float* ys = (float*)smem;               // 128 x YSTRIDE fp32 (133120 B)
    #pragma unroll
    for (int ms = 0; ms < 4; ms++)
        #pragma unroll
        for (int half = 0; half < 2; half++) {
            int rl = warpM * 64 + ms * 16 + half * 8 + gid;
            #pragma unroll
            for (int ns = 0; ns < 8; ns++) {
                int col = warpN * 64 + ns * 8 + tig * 2;
                ys[rl * YSTRIDE + col]     = acc[ms][ns][half * 2 + 0];
                ys[rl * YSTRIDE + col + 1] = acc[ms][ns][half * 2 + 1];
            }
        }

    __syncthreads();
    if (t == 0) { while (*(volatile unsigned*)&g_bar < GRID_GEMM) { } }
    __syncthreads();

    // ---- per-channel sc/mb (one thread per channel) ----
    float* sc = ys + 128 * YSTRIDE;         // 256 floats
    float* mb = sc + 256;                   // 256 floats
    {
        const float inv = 1.f / N_;
        float sm_ = __ldcg(&g_sum[b * C_ + t]);
        float sq_ = __ldcg(&g_sumsq[b * C_ + t]);
        float mu = sm_ * inv;
        float rs = rsqrtf(sq_ * inv - mu * mu + 1e-6f);
        float s = ls[t] * rs;
        sc[t] = s;
        mb[t] = lb[t] - mu * s;
    }
    __syncthreads();

    // ---- coalesced apply: out = relu(y*sc + mb) + X ----
    #pragma unroll 4
    for (int it = 0; it < 32; it++) {
        int slot = it * 256 + t;            // 8192 float4 slots
        int row = slot >> 6, c4 = slot & 63;
        float4 y = *(float4*)&ys[row * YSTRIDE + c4 * 4];
        float4 s4 = *(float4*)&sc[c4 * 4];
        float4 m4 = *(float4*)&mb[c4 * 4];
        const float* xp = X + (size_t)(m0 + row) * C_ + c4 * 4;
        float4 x = *(const float4*)xp;
        float4 o;
        o.x = fmaxf(y.x * s4.x + m4.x, 0.f) + x.x;
        o.y = fmaxf(y.y * s4.y + m4.y, 0.f) + x.y;
        o.z = fmaxf(y.z * s4.z + m4.z, 0.f) + x.z;
        o.w = fmaxf(y.w * s4.w + m4.w, 0.f) + x.w;
        *(float4*)(out + (size_t)(m0 + row) * C_ + c4 * 4) = o;
    }
}

// ---------------------------------------------------------------------------
extern "C" void kernel_launch(void* const* d_in, const int* in_sizes, int n_in,
                              void* d_out, int out_size) {
    // order: inputs, mask, Wq, bq, Wk, bk, Wv, bv, Wo, bo, ln_scale, ln_bias
    const float* X  = (const float*)d_in[0];
    const float* Wv = (const float*)d_in[6];
    const float* Wo = (const float*)d_in[8];
    const float* ls = (const float*)d_in[10];
    const float* lb = (const float*)d_in[11];
    float* out = (float*)d_out;

    cudaFuncSetAttribute(k_gemm, cudaFuncAttributeMaxDynamicSharedMemorySize,
                         SM_TOTAL);

    k_prepmm<<<dim3(32, 8), 256>>>(Wv, Wo);
    k_split<<<64, 256>>>();
    k_gemm<<<GRID_GEMM, 256, SM_TOTAL>>>(X, ls, lb, out);
}

// round 8
// speedup vs baseline: 1.1205x; 1.0098x over previous
#include <cuda_runtime.h>
#include <cuda_bf16.h>
#include <cstdint>

#define B_ 4
#define N_ 4096
#define C_ 256
#define M_ (B_ * N_)

#define ROWB 144      // bytes per SMEM row (64 bf16 = 128B + 16B pad)

// SMEM layout (dynamic) for k_gemm:
#define SM_AHI 0
#define SM_ALO 18432
#define SM_B0  36864            // buffer 0: hi at +0, lo at +36864
#define BUFSZ  73728
#define SM_TOTAL (36864 + 2 * BUFSZ)   // 184320

#define GRID_GEMM 128
#define YSTRIDE 260             // fp32 words per staged y row (padded)

// ---------------- device scratch ----------------
__device__ __nv_bfloat16 g_Bhi[C_ * C_];   // W^T hi, [n][k]
__device__ __nv_bfloat16 g_Blo[C_ * C_];   // W^T lo, [n][k]
__device__ float g_sum[B_ * C_];
__device__ float g_sumsq[B_ * C_];
__device__ unsigned g_bar;                 // grid barrier (zeroed by k_prep2)

__device__ __forceinline__ uint32_t smem_u32(const void* p) {
    uint32_t a;
    asm("{ .reg .u64 t; cvta.to.shared.u64 t, %1; cvt.u32.u64 %0, t; }" : "=r"(a) : "l"(p));
    return a;
}
__device__ __forceinline__ void cp16(uint32_t dst, const void* src) {
    asm volatile("cp.async.cg.shared.global [%0], [%1], 16;" :: "r"(dst), "l"(src));
}
__device__ __forceinline__ void cp_commit() {
    asm volatile("cp.async.commit_group;" ::: "memory");
}
template <int N> __device__ __forceinline__ void cp_wait() {
    asm volatile("cp.async.wait_group %0;" :: "n"(N) : "memory");
}
__device__ __forceinline__ void ldmx4(uint32_t* r, uint32_t addr) {
    asm volatile("ldmatrix.sync.aligned.m8n8.x4.shared.b16 {%0,%1,%2,%3}, [%4];"
                 : "=r"(r[0]), "=r"(r[1]), "=r"(r[2]), "=r"(r[3]) : "r"(addr));
}
__device__ __forceinline__ void ldmx2(uint32_t* r, uint32_t addr) {
    asm volatile("ldmatrix.sync.aligned.m8n8.x2.shared.b16 {%0,%1}, [%2];"
                 : "=r"(r[0]), "=r"(r[1]) : "r"(addr));
}
__device__ __forceinline__ void mma16816(float* c, const uint32_t* a, const uint32_t* b) {
    asm volatile(
        "mma.sync.aligned.m16n8k16.row.col.f32.bf16.bf16.f32 "
        "{%0,%1,%2,%3}, {%4,%5,%6,%7}, {%8,%9}, {%0,%1,%2,%3};"
        : "+f"(c[0]), "+f"(c[1]), "+f"(c[2]), "+f"(c[3])
        : "r"(a[0]), "r"(a[1]), "r"(a[2]), "r"(a[3]), "r"(b[0]), "r"(b[1]));
}

// ---------------------------------------------------------------------------
// K1: W row i = Wv[i,:] @ Wo  (one CTA per row, full k-reduction, MLP-32).
// Emits transposed bf16 hi/lo directly; CTA 0 zeroes stats + barrier.
// (Per-channel bias cancels exactly through the N-axis LayerNorm -> dropped.)
// ---------------------------------------------------------------------------
__global__ __launch_bounds__(256) void k_prep2(const float* __restrict__ Wv,
                                               const float* __restrict__ Wo) {
    __shared__ float s_wv[C_];
    int t = threadIdx.x;
    int i = blockIdx.x;                  // W row index (= k index of B operand)
    s_wv[t] = Wv[i * C_ + t];
    __syncthreads();

    float acc = 0.f;
    for (int m0 = 0; m0 < C_; m0 += 32) {
        float w[32];
        #pragma unroll
        for (int u = 0; u < 32; u++) w[u] = Wo[(m0 + u) * C_ + t];
        #pragma unroll
        for (int u = 0; u < 32; u++) acc += s_wv[m0 + u] * w[u];
    }
    __nv_bfloat16 h = __float2bfloat16(acc);
    g_Bhi[t * C_ + i] = h;                               // B operand = W^T
    g_Blo[t * C_ + i] = __float2bfloat16(acc - __bfloat162float(h));

    if (i == 0) {
        float4 z = make_float4(0.f, 0.f, 0.f, 0.f);
        *(float4*)&g_sum[t * 4] = z;                     // 256*4 = 1024 floats
        *(float4*)&g_sumsq[t * 4] = z;
        if (t == 0) g_bar = 0u;
    }
}

// ---------------------------------------------------------------------------
// K2: y = X @ W (split-bf16 HMMA) fully fused:
//     stats atomics -> grid barrier (overlapped with smem y staging)
//     -> coalesced LN+relu+residual apply from smem.
// ---------------------------------------------------------------------------
__global__ __launch_bounds__(256, 1) void k_gemm(const float* __restrict__ X,
                                                 const float* __restrict__ ls,
                                                 const float* __restrict__ lb,
                                                 float* __restrict__ out) {
    extern __shared__ char smem[];
    uint32_t sb = smem_u32(smem);
    int t = threadIdx.x, wid = t >> 5, lane = t & 31;
    int warpM = wid >> 2, warpN = wid & 3;
    int m0 = blockIdx.x * 128;
    int q = t & 3, rr = t >> 2;          // loader coords

    float acc[4][8][4];
    #pragma unroll
    for (int i = 0; i < 4; i++)
        #pragma unroll
        for (int j = 0; j < 8; j++)
            #pragma unroll
            for (int r = 0; r < 4; r++) acc[i][j][r] = 0.f;

    uint32_t aBase = sb + SM_AHI +
        (warpM * 64 + ((lane >> 3) & 1) * 8 + (lane & 7)) * ROWB + (lane >> 4) * 16;

    auto issueB = [&](int c, int buf) {
        uint32_t bhi = sb + SM_B0 + buf * BUFSZ;
        uint32_t blo = bhi + 36864;
        const char* shi = (const char*)g_Bhi + c * 128 + q * 32;
        const char* slo = (const char*)g_Blo + c * 128 + q * 32;
        #pragma unroll
        for (int it = 0; it < 4; it++) {
            int row = it * 64 + rr;
            uint32_t d = row * ROWB + q * 32;
            const char* sh = shi + (size_t)row * 512;
            const char* sl = slo + (size_t)row * 512;
            cp16(bhi + d, sh);       cp16(bhi + d + 16, sh + 16);
            cp16(blo + d, sl);       cp16(blo + d + 16, sl + 16);
        }
        cp_commit();
    };
    float areg[32];
    auto loadA = [&](int c) {
        #pragma unroll
        for (int p = 0; p < 2; p++) {
            const float* src = X + (size_t)(m0 + p * 64 + rr) * C_ + c * 64 + q * 16;
            #pragma unroll
            for (int i = 0; i < 4; i++)
                *(float4*)&areg[p * 16 + i * 4] = *(const float4*)(src + i * 4);
        }
    };
    auto storeA = [&]() {
        #pragma unroll
        for (int p = 0; p < 2; p++) {
            int row = p * 64 + rr;
            __nv_bfloat16 h[16], l[16];
            #pragma unroll
            for (int i = 0; i < 16; i++) {
                float v = areg[p * 16 + i];
                h[i] = __float2bfloat16(v);
                l[i] = __float2bfloat16(v - __bfloat162float(h[i]));
            }
            char* dh = smem + SM_AHI + row * ROWB + q * 32;
            char* dl = smem + SM_ALO + row * ROWB + q * 32;
            *(uint4*)dh = *(uint4*)&h[0]; *(uint4*)(dh + 16) = *(uint4*)&h[8];
            *(uint4*)dl = *(uint4*)&l[0]; *(uint4*)(dl + 16) = *(uint4*)&l[8];
        }
    };

    issueB(0, 0);
    loadA(0);

    for (int c = 0; c < 4; c++) {
        if (c < 3) issueB(c + 1, (c + 1) & 1);
        storeA();
        if (c < 3) cp_wait<1>(); else cp_wait<0>();
        __syncthreads();
        if (c < 3) loadA(c + 1);           // DRAM latency hides under MMAs

        uint32_t bBase = sb + SM_B0 + (c & 1) * BUFSZ +
            (warpN * 64 + (lane & 7)) * ROWB + ((lane >> 3) & 1) * 16;
        #pragma unroll
        for (int ks = 0; ks < 4; ks++) {
            uint32_t ah[4][4], al[4][4];
            #pragma unroll
            for (int ms = 0; ms < 4; ms++) {
                uint32_t addr = aBase + ms * (16 * ROWB) + ks * 32;
                ldmx4(ah[ms], addr);
                ldmx4(al[ms], addr + (SM_ALO - SM_AHI));
            }
            #pragma unroll
            for (int ns = 0; ns < 8; ns++) {
                uint32_t bh[2], bl[2];
                uint32_t addr = bBase + ns * (8 * ROWB) + ks * 32;
                ldmx2(bh, addr);
                ldmx2(bl, addr + 36864);
                #pragma unroll
                for (int ms = 0; ms < 4; ms++) {
                    mma16816(acc[ms][ns], ah[ms], bh);
                    mma16816(acc[ms][ns], ah[ms], bl);
                    mma16816(acc[ms][ns], al[ms], bh);
                }
            }
        }
        __syncthreads();
    }

    // ---- column stats from registers, atomics into g_sum/g_sumsq ----
    int b = m0 >> 12;
    int gid = lane >> 2, tig = lane & 3;
    #pragma unroll
    for (int ns = 0; ns < 8; ns++) {
        float s0 = 0.f, s1 = 0.f, q0 = 0.f, q1 = 0.f;
        #pragma unroll
        for (int ms = 0; ms < 4; ms++)
            #pragma unroll
            for (int half = 0; half < 2; half++) {
                float v0 = acc[ms][ns][half * 2 + 0];
                float v1 = acc[ms][ns][half * 2 + 1];
                s0 += v0; q0 += v0 * v0;
                s1 += v1; q1 += v1 * v1;
            }
        #pragma unroll
        for (int off = 4; off < 32; off <<= 1) {
            s0 += __shfl_xor_sync(0xFFFFFFFFu, s0, off);
            s1 += __shfl_xor_sync(0xFFFFFFFFu, s1, off);
            q0 += __shfl_xor_sync(0xFFFFFFFFu, q0, off);
            q1 += __shfl_xor_sync(0xFFFFFFFFu, q1, off);
        }
        if (gid == 0) {
            int col = warpN * 64 + ns * 8 + tig * 2;
            atomicAdd(&g_sum[b * C_ + col],     s0);
            atomicAdd(&g_sum[b * C_ + col + 1], s1);
            atomicAdd(&g_sumsq[b * C_ + col],     q0);
            atomicAdd(&g_sumsq[b * C_ + col + 1], q1);
        }
    }

    // ---- arrive, then stage y into smem while other CTAs drain ----
    __threadfence();
    __syncthreads();
    if (t == 0) atomicAdd(&g_bar, 1u);

    float* ys = (float*)smem;               // 128 x YSTRIDE fp32 (133120 B)
    #pragma unroll
    for (int ms = 0; ms < 4; ms++)
        #pragma unroll
        for (int half = 0; half < 2; half++) {
            int rl = warpM * 64 + ms * 16 + half * 8 + gid;
            #pragma unroll
            for (int ns = 0; ns < 8; ns++) {
                int col = warpN * 64 + ns * 8 + tig * 2;
                ys[rl * YSTRIDE + col]     = acc[ms][ns][half * 2 + 0];
                ys[rl * YSTRIDE + col + 1] = acc[ms][ns][half * 2 + 1];
            }
        }

    __syncthreads();
    if (t == 0) { while (*(volatile unsigned*)&g_bar < GRID_GEMM) { } }
    __syncthreads();

    // ---- per-channel sc/mb (one thread per channel) ----
    float* sc = ys + 128 * YSTRIDE;         // 256 floats
    float* mb = sc + 256;                   // 256 floats
    {
        const float inv = 1.f / N_;
        float sm_ = __ldcg(&g_sum[b * C_ + t]);
        float sq_ = __ldcg(&g_sumsq[b * C_ + t]);
        float mu = sm_ * inv;
        float rs = rsqrtf(sq_ * inv - mu * mu + 1e-6f);
        float s = ls[t] * rs;
        sc[t] = s;
        mb[t] = lb[t] - mu * s;
    }
    __syncthreads();

    // ---- coalesced apply: out = relu(y*sc + mb) + X ----
    #pragma unroll 4
    for (int it = 0; it < 32; it++) {
        int slot = it * 256 + t;            // 8192 float4 slots
        int row = slot >> 6, c4 = slot & 63;
        float4 y = *(float4*)&ys[row * YSTRIDE + c4 * 4];
        float4 s4 = *(float4*)&sc[c4 * 4];
        float4 m4 = *(float4*)&mb[c4 * 4];
        const float* xp = X + (size_t)(m0 + row) * C_ + c4 * 4;
        float4 x = *(const float4*)xp;
        float4 o;
        o.x = fmaxf(y.x * s4.x + m4.x, 0.f) + x.x;
        o.y = fmaxf(y.y * s4.y + m4.y, 0.f) + x.y;
        o.z = fmaxf(y.z * s4.z + m4.z, 0.f) + x.z;
        o.w = fmaxf(y.w * s4.w + m4.w, 0.f) + x.w;
        *(float4*)(out + (size_t)(m0 + row) * C_ + c4 * 4) = o;
    }
}

// ---------------------------------------------------------------------------
extern "C" void kernel_launch(void* const* d_in, const int* in_sizes, int n_in,
                              void* d_out, int out_size) {
    // order: inputs, mask, Wq, bq, Wk, bk, Wv, bv, Wo, bo, ln_scale, ln_bias
    const float* X  = (const float*)d_in[0];
    const float* Wv = (const float*)d_in[6];
    const float* Wo = (const float*)d_in[8];
    const float* ls = (const float*)d_in[10];
    const float* lb = (const float*)d_in[11];
    float* out = (float*)d_out;

    cudaFuncSetAttribute(k_gemm, cudaFuncAttributeMaxDynamicSharedMemorySize,
                         SM_TOTAL);

    k_prep2<<<C_, 256>>>(Wv, Wo);
    k_gemm<<<GRID_GEMM, 256, SM_TOTAL>>>(X, ls, lb, out);
}